// round 11
// baseline (speedup 1.0000x reference)
#include <cuda_runtime.h>
#include <cstdint>

#define HD 128
#define MAXN 40000
#define MAXR 8
#define MAXE 640000
#define MAXNR (MAXN * MAXR)
#define MPADC (((MAXN + 127) / 128) * 128)

/* ---------------- scratch (static device globals; no allocation) ------------- */
__device__ float g_w[MAXR * HD * HD];
__device__ float g_h[(size_t)MPADC * HD];
__device__ float g_nbr[(size_t)MPADC * HD];
__device__ int   g_deg2[MAXNR];
__device__ int   g_rsx[MAXNR + 1];
__device__ int   g_cur2[MAXNR];
__device__ int   g_csrc[MAXE];
__device__ int   g_bsum[512], g_boff[512];
__device__ int   g_done;
__device__ unsigned g_mxs[4];   /* abs-max bits: 0=x, 1=w+root, 2=h/nbr, 3=wrel/wroot2 */
/* int8 two-level A images (uint32 = 4 int8 along k; row = 32 u32):
   layer-1 chunks 0..7 = S_r, chunk 8 = X ; layer-2 chunk 0 = nbr, 1 = h */
__device__ uint32_t g_aq1[(size_t)9 * MPADC * 32];
__device__ uint32_t g_aq2[(size_t)9 * MPADC * 32];
__device__ uint32_t g_a2q1[(size_t)2 * MPADC * 32];
__device__ uint32_t g_a2q2[(size_t)2 * MPADC * 32];
/* B images: [slot][n=128][k row = 32 u32]; slots 0..7 w[r], 8 root, 9 wrel, 10 wroot2 */
__device__ uint32_t g_bq1[11 * 128 * 32];
__device__ uint32_t g_bq2[11 * 128 * 32];

/* ---------------- helpers ---------------------------------------------------- */
__device__ __forceinline__ uint32_t smem_u32(const void* p) {
    uint32_t a;
    asm("{ .reg .u64 t; cvta.to.shared.u64 t, %1; cvt.u32.u64 %0, t; }" : "=r"(a) : "l"(p));
    return a;
}
/* two-level int8 quant: v = s*q1 + (s/256)*q2, s = max/127, inv = 127/max */
__device__ __forceinline__ void qpack(float4 v, float inv, uint32_t& p1, uint32_t& p2) {
    float d0 = v.x * inv, d1 = v.y * inv, d2 = v.z * inv, d3 = v.w * inv;
    int a0 = __float2int_rn(d0), a1 = __float2int_rn(d1);
    int a2 = __float2int_rn(d2), a3 = __float2int_rn(d3);
    int b0 = min(127, __float2int_rn((d0 - (float)a0) * 256.f));
    int b1 = min(127, __float2int_rn((d1 - (float)a1) * 256.f));
    int b2 = min(127, __float2int_rn((d2 - (float)a2) * 256.f));
    int b3 = min(127, __float2int_rn((d3 - (float)a3) * 256.f));
    p1 = (uint32_t)(a0 & 255) | ((uint32_t)(a1 & 255) << 8) |
         ((uint32_t)(a2 & 255) << 16) | ((uint32_t)(a3 & 255) << 24);
    p2 = (uint32_t)(b0 & 255) | ((uint32_t)(b1 & 255) << 8) |
         ((uint32_t)(b2 & 255) << 16) | ((uint32_t)(b3 & 255) << 24);
}
__device__ __forceinline__ void warp_amax(float m, int slot) {
#pragma unroll
    for (int off = 16; off > 0; off >>= 1)
        m = fmaxf(m, __shfl_xor_sync(0xffffffffu, m, off));
    if ((threadIdx.x & 31) == 0) atomicMax(&g_mxs[slot], __float_as_uint(m));
}

#define LDSM4(r, addr)                                                             \
    asm volatile("ldmatrix.sync.aligned.m8n8.x4.shared.b16 {%0,%1,%2,%3}, [%4];"   \
        : "=r"((r)[0]), "=r"((r)[1]), "=r"((r)[2]), "=r"((r)[3]) : "r"(addr))

#define MMAS8(c, a, b0, b1)                                                        \
    asm volatile("mma.sync.aligned.m16n8k32.row.col.s32.s8.s8.s32 "                \
        "{%0,%1,%2,%3}, {%4,%5,%6,%7}, {%8,%9}, {%0,%1,%2,%3};"                    \
        : "+r"((c)[0]), "+r"((c)[1]), "+r"((c)[2]), "+r"((c)[3])                   \
        : "r"((a)[0]), "r"((a)[1]), "r"((a)[2]), "r"((a)[3]), "r"(b0), "r"(b1))

#define CPASYNC16(saddr, gptr)                                                     \
    asm volatile("cp.async.cg.shared.global [%0], [%1], 16;"                       \
        :: "r"(saddr), "l"(gptr))
#define CPCOMMIT() asm volatile("cp.async.commit_group;" ::: "memory")

/* ---------------- maxima ------------------------------------------------------ */
__global__ void k_maxinit() { if (threadIdx.x < 4) g_mxs[threadIdx.x] = 0u; }

__global__ void k_maxabs(const float* __restrict__ p, size_t n, int slot) {
    size_t i = (size_t)blockIdx.x * blockDim.x + threadIdx.x;
    size_t st = (size_t)gridDim.x * blockDim.x;
    float m = 0.f;
    for (; i < n; i += st) m = fmaxf(m, fabsf(p[i]));
    warp_amax(m, slot);
}
/* root -> slot1 ; wrel, wroot2 -> slot3 (each 16384 floats, 16 blocks apiece) */
__global__ void k_maxabs3(const float* __restrict__ root, const float* __restrict__ wrel,
                          const float* __restrict__ wroot2) {
    int which = blockIdx.x >> 4, sub = blockIdx.x & 15;
    const float* p = (which == 0) ? root : (which == 1) ? wrel : wroot2;
    int slot = (which == 0) ? 1 : 3;
    int base = sub * 1024 + threadIdx.x;
    float m = 0.f;
#pragma unroll
    for (int i = 0; i < 4; i++) m = fmaxf(m, fabsf(p[base + i * 256]));
    warp_amax(m, slot);
}

/* ---------------- prep kernels ------------------------------------------------ */
__global__ void k_compute_w(const float* __restrict__ comp,
                            const float* __restrict__ basis, int R, int B) {
    int rd = blockIdx.x, h = threadIdx.x;
    int r = rd / HD, d = rd % HD;
    float s = 0.f;
    for (int b = 0; b < B; b++)
        s += comp[r * B + b] * basis[((size_t)b * HD + d) * HD + h];
    g_w[(size_t)rd * HD + h] = s;
    warp_amax(fabsf(s), 1);
}

/* B images: img[slot][n][k] = quant(W[k][n]) */
__global__ void k_prep_b(const float* __restrict__ root, const float* __restrict__ wrel,
                         const float* __restrict__ wroot2) {
    int slot = blockIdx.x;
    const float* W = (slot < 8) ? (g_w + (size_t)slot * HD * HD)
                   : (slot == 8) ? root : (slot == 9) ? wrel : wroot2;
    float mx = __uint_as_float(g_mxs[(slot < 9) ? 1 : 3]);
    float inv = 127.f / mx;
    for (int i = threadIdx.x; i < 128 * 32; i += blockDim.x) {
        int n = i >> 5, k4 = i & 31;
        float4 v = make_float4(W[(size_t)(k4 * 4 + 0) * HD + n],
                               W[(size_t)(k4 * 4 + 1) * HD + n],
                               W[(size_t)(k4 * 4 + 2) * HD + n],
                               W[(size_t)(k4 * 4 + 3) * HD + n]);
        uint32_t p1, p2;
        qpack(v, inv, p1, p2);
        g_bq1[slot * 4096 + i] = p1;
        g_bq2[slot * 4096 + i] = p2;
    }
}

/* ---------------- per-(dst,rel) CSR ------------------------------------------ */
__global__ void k_hist(const int* __restrict__ ei, const int* __restrict__ et,
                       int E, int R) {
    int e = blockIdx.x * blockDim.x + threadIdx.x;
    if (e < E) atomicAdd(&g_deg2[ei[E + e] * R + et[e]], 1);
}

__global__ void __launch_bounds__(1024) k_scan(int n, int nblk) {
    __shared__ int swarp[32];
    __shared__ int sticket;
    int b = blockIdx.x, t = threadIdx.x, i = b * 1024 + t;
    int lane = t & 31, w = t >> 5;
    int v = 0;
    if (i < n) { v = g_deg2[i]; g_deg2[i] = 0; g_cur2[i] = 0; }
    int x = v;
#pragma unroll
    for (int off = 1; off < 32; off <<= 1) {
        int y = __shfl_up_sync(0xffffffffu, x, off);
        if (lane >= off) x += y;
    }
    if (lane == 31) swarp[w] = x;
    __syncthreads();
    if (w == 0) {
        int s = swarp[lane];
#pragma unroll
        for (int off = 1; off < 32; off <<= 1) {
            int y = __shfl_up_sync(0xffffffffu, s, off);
            if (lane >= off) s += y;
        }
        swarp[lane] = s;
    }
    __syncthreads();
    int inc = x + ((w > 0) ? swarp[w - 1] : 0);
    int ex = inc - v;
    if (i < n) g_rsx[i] = ex;
    if (i == n - 1) g_rsx[n] = ex + v;
    if (t == 1023) g_bsum[b] = inc;
    __threadfence();
    if (t == 0) sticket = atomicAdd(&g_done, 1);
    __syncthreads();
    if (sticket == (int)gridDim.x - 1) {
        int v2 = 0, x2 = 0;
        if (t < 512) {
            v2 = (t < nblk) ? *((volatile int*)&g_bsum[t]) : 0;
            x2 = v2;
#pragma unroll
            for (int off = 1; off < 32; off <<= 1) {
                int y = __shfl_up_sync(0xffffffffu, x2, off);
                if (lane >= off) x2 += y;
            }
            if (lane == 31) swarp[w] = x2;
        }
        __syncthreads();
        if (w == 0 && lane < 16) {
            int s = swarp[lane];
#pragma unroll
            for (int off = 1; off < 16; off <<= 1) {
                int y = __shfl_up_sync(0x0000ffffu, s, off);
                if (lane >= off) s += y;
            }
            swarp[lane] = s;
        }
        __syncthreads();
        if (t < 512 && t < nblk)
            g_boff[t] = x2 + ((w > 0) ? swarp[w - 1] : 0) - v2;
        if (t == 0) g_done = 0;
    }
}

__global__ void k_scatter(const int* __restrict__ ei, const int* __restrict__ et,
                          int E, int R) {
    int e = blockIdx.x * blockDim.x + threadIdx.x;
    if (e >= E) return;
    int seg = ei[E + e] * R + et[e];
    int pos = g_rsx[seg] + g_boff[seg >> 10] + atomicAdd(&g_cur2[seg], 1);
    g_csrc[pos] = ei[e];
}

/* ---------------- S builder: quantized per-relation mean sums ----------------- */
__global__ void __launch_bounds__(256) k_aggx(const float* __restrict__ x,
                                              int N, int mpad, size_t chU) {
    int gt = blockIdx.x * blockDim.x + threadIdx.x;
    int node = gt >> 5, lane = gt & 31;
    if (node >= mpad) return;
    bool real = node < N;
    float invq = 127.f / __uint_as_float(g_mxs[0]);
    uint32_t bd = 0;
    if (real && lane < 9) {
        int seg = node * 8 + lane;
        bd = (uint32_t)(g_rsx[seg] + g_boff[seg >> 10]);
    }
    uint32_t a0 = __shfl_sync(0xffffffffu, bd, 0);
    uint32_t a8 = __shfl_sync(0xffffffffu, bd, 8);
    float inv = 1.f / fmaxf((float)(int)(a8 - a0), 1.f);
    size_t rowOff = (size_t)node * 32 + lane;

#pragma unroll
    for (int r = 0; r < 8; r++) {
        uint32_t s0 = __shfl_sync(0xffffffffu, bd, r);
        uint32_t s1 = __shfl_sync(0xffffffffu, bd, r + 1);
        float4 acc = make_float4(0.f, 0.f, 0.f, 0.f);
        uint32_t i = s0;
        for (; i + 2 <= s1; i += 2) {
            int sa = g_csrc[i], sb = g_csrc[i + 1];
            float4 va = ((const float4*)x)[(size_t)sa * 32 + lane];
            float4 vb = ((const float4*)x)[(size_t)sb * 32 + lane];
            acc.x += va.x + vb.x; acc.y += va.y + vb.y;
            acc.z += va.z + vb.z; acc.w += va.w + vb.w;
        }
        if (i < s1) {
            float4 va = ((const float4*)x)[(size_t)g_csrc[i] * 32 + lane];
            acc.x += va.x; acc.y += va.y; acc.z += va.z; acc.w += va.w;
        }
        acc.x *= inv; acc.y *= inv; acc.z *= inv; acc.w *= inv;
        uint32_t p1, p2;
        qpack(acc, invq, p1, p2);
        g_aq1[(size_t)r * chU + rowOff] = p1;
        g_aq2[(size_t)r * chU + rowOff] = p2;
    }
    float4 xv = make_float4(0.f, 0.f, 0.f, 0.f);
    if (real) xv = ((const float4*)x)[(size_t)node * 32 + lane];
    uint32_t p1, p2;
    qpack(xv, invq, p1, p2);
    g_aq1[(size_t)8 * chU + rowOff] = p1;
    g_aq2[(size_t)8 * chU + rowOff] = p2;
}

/* ---------------- layer-2 neighbor sum (f32 + max) ---------------------------- */
__global__ void __launch_bounds__(256) k_agg2(int N, int mpad) {
    int gt = blockIdx.x * blockDim.x + threadIdx.x;
    int node = gt >> 5, lane = gt & 31;
    if (node >= N) return;
    int s = node * 8, s2 = s + 8;
    uint32_t a0 = (uint32_t)(g_rsx[s] + g_boff[s >> 10]);
    uint32_t a8 = (uint32_t)(g_rsx[s2] + g_boff[s2 >> 10]);
    float4 acc = make_float4(0.f, 0.f, 0.f, 0.f);
    uint32_t i = a0;
    for (; i + 4 <= a8; i += 4) {
        int s0 = g_csrc[i], s1 = g_csrc[i + 1], sx = g_csrc[i + 2], s3 = g_csrc[i + 3];
        float4 v0 = ((const float4*)g_h)[(size_t)s0 * 32 + lane];
        float4 v1 = ((const float4*)g_h)[(size_t)s1 * 32 + lane];
        float4 v2 = ((const float4*)g_h)[(size_t)sx * 32 + lane];
        float4 v3 = ((const float4*)g_h)[(size_t)s3 * 32 + lane];
        acc.x += (v0.x + v1.x) + (v2.x + v3.x);
        acc.y += (v0.y + v1.y) + (v2.y + v3.y);
        acc.z += (v0.z + v1.z) + (v2.z + v3.z);
        acc.w += (v0.w + v1.w) + (v2.w + v3.w);
    }
    for (; i < a8; i++) {
        float4 v = ((const float4*)g_h)[(size_t)g_csrc[i] * 32 + lane];
        acc.x += v.x; acc.y += v.y; acc.z += v.z; acc.w += v.w;
    }
    ((float4*)g_nbr)[(size_t)node * 32 + lane] = acc;
    float m = fmaxf(fmaxf(fabsf(acc.x), fabsf(acc.y)), fmaxf(fabsf(acc.z), fabsf(acc.w)));
    warp_amax(m, 2);
}

/* ---------------- quantize nbr & h -> layer-2 A images ------------------------ */
__global__ void __launch_bounds__(256) k_quant2(int N, int mpad, size_t chU) {
    int t = blockIdx.x * blockDim.x + threadIdx.x;
    if (t >= mpad * 32) return;
    int node = t >> 5;
    float inv = 127.f / __uint_as_float(g_mxs[2]);
    float4 vn = make_float4(0.f, 0.f, 0.f, 0.f), vh = vn;
    if (node < N) {
        vn = ((const float4*)g_nbr)[t];
        vh = ((const float4*)g_h)[t];
    }
    uint32_t p1, p2;
    qpack(vn, inv, p1, p2);
    g_a2q1[t] = p1; g_a2q2[t] = p2;
    qpack(vh, inv, p1, p2);
    g_a2q1[chU + t] = p1; g_a2q2[chU + t] = p2;
}

/* ---------------- cp.async 2-stage int8 two-level mma GEMM -------------------- */
/* M-tile 64, N=128, K=128/chunk (4 k-steps of k32); smem row pitch 144 B        */
#define PITCH8 144
#define S8_A1 0
#define S8_A2 9216
#define S8_B1 18432
#define S8_B2 36864
#define S8_STG 55296
#define S8_PIPE (2 * S8_STG)

__device__ __forceinline__ void prefetch8(uint32_t sb,
    const uint32_t* __restrict__ a1, const uint32_t* __restrict__ a2,
    const uint32_t* __restrict__ b1, const uint32_t* __restrict__ b2, int tid)
{
#pragma unroll
    for (int i = 0; i < 4; i++) {           /* A: 2 levels x 64 rows x 8 segs */
        int idx = tid + i * 256;
        int lev = idx >> 9, rr = (idx >> 3) & 63, c = idx & 7;
        const uint32_t* s = (lev ? a2 : a1) + rr * 32 + c * 4;
        CPASYNC16(sb + (lev ? S8_A2 : S8_A1) + rr * PITCH8 + c * 16, s);
    }
#pragma unroll
    for (int i = 0; i < 8; i++) {           /* B: 2 levels x 128 rows x 8 segs */
        int idx = tid + i * 256;
        int lev = idx >> 10, rr = (idx >> 3) & 127, c = idx & 7;
        const uint32_t* s = (lev ? b2 : b1) + rr * 32 + c * 4;
        CPASYNC16(sb + (lev ? S8_B2 : S8_B1) + rr * PITCH8 + c * 16, s);
    }
}

template<int WMAX>
__global__ void __launch_bounds__(256) k_mma(
    const uint32_t* __restrict__ aQ1, const uint32_t* __restrict__ aQ2,
    size_t aStrideU, int nch, int bslot0, int aslot, int bslot,
    const float* __restrict__ bias, float* __restrict__ Cf, int M)
{
    extern __shared__ unsigned char sm[];
    uint32_t sb0 = smem_u32(sm);
    int tid = threadIdx.x, lane = tid & 31, wid = tid >> 5;
    int row0 = blockIdx.x * 64;
    int mrow0 = (wid & 1) * 32, ncol0 = (wid >> 1) * 32;

    int aM[2][4][4], aS[2][4][4];
#pragma unroll
    for (int a = 0; a < 2; a++)
#pragma unroll
        for (int b = 0; b < 4; b++)
#pragma unroll
            for (int c = 0; c < 4; c++) { aM[a][b][c] = 0; aS[a][b][c] = 0; }

    prefetch8(sb0, aQ1 + (size_t)row0 * 32, aQ2 + (size_t)row0 * 32,
              g_bq1 + (size_t)bslot0 * 4096, g_bq2 + (size_t)bslot0 * 4096, tid);
    CPCOMMIT();

    for (int ch = 0; ch < nch; ch++) {
        if (ch + 1 < nch) {
            size_t ao = (size_t)(ch + 1) * aStrideU + (size_t)row0 * 32;
            size_t bo = (size_t)(bslot0 + ch + 1) * 4096;
            prefetch8(sb0 + ((ch + 1) & 1) * S8_STG, aQ1 + ao, aQ2 + ao,
                      g_bq1 + bo, g_bq2 + bo, tid);
            CPCOMMIT();
            asm volatile("cp.async.wait_group 1;" ::: "memory");
        } else {
            asm volatile("cp.async.wait_group 0;" ::: "memory");
        }
        __syncthreads();

        uint32_t sbase = sb0 + (ch & 1) * S8_STG;
#pragma unroll
        for (int ks = 0; ks < 4; ks++) {
            uint32_t koff = ks * 32 + (lane >> 4) * 16;
            uint32_t a1f[2][4], a2f[2][4], b1f[2][4], b2f[2][4];
#pragma unroll
            for (int mf = 0; mf < 2; mf++) {
                uint32_t arow = (uint32_t)(mrow0 + mf * 16 + (lane & 15)) * PITCH8 + koff;
                LDSM4(a1f[mf], sbase + S8_A1 + arow);
                LDSM4(a2f[mf], sbase + S8_A2 + arow);
            }
#pragma unroll
            for (int nf2 = 0; nf2 < 2; nf2++) {
                uint32_t brow = (uint32_t)(ncol0 + nf2 * 16 + (lane & 15)) * PITCH8 + koff;
                LDSM4(b1f[nf2], sbase + S8_B1 + brow);
                LDSM4(b2f[nf2], sbase + S8_B2 + brow);
            }
#pragma unroll
            for (int nf2 = 0; nf2 < 2; nf2++)
#pragma unroll
                for (int mf = 0; mf < 2; mf++)
#pragma unroll
                    for (int nfr = 0; nfr < 2; nfr++)
                        MMAS8(aM[mf][nf2 * 2 + nfr], a1f[mf],
                              b1f[nf2][nfr], b1f[nf2][nfr + 2]);      /* q1*q1 */
#pragma unroll
            for (int nf2 = 0; nf2 < 2; nf2++)
#pragma unroll
                for (int mf = 0; mf < 2; mf++)
#pragma unroll
                    for (int nfr = 0; nfr < 2; nfr++)
                        MMAS8(aS[mf][nf2 * 2 + nfr], a1f[mf],
                              b2f[nf2][nfr], b2f[nf2][nfr + 2]);      /* q1*q2 */
#pragma unroll
            for (int nf2 = 0; nf2 < 2; nf2++)
#pragma unroll
                for (int mf = 0; mf < 2; mf++)
#pragma unroll
                    for (int nfr = 0; nfr < 2; nfr++)
                        MMAS8(aS[mf][nf2 * 2 + nfr], a2f[mf],
                              b1f[nf2][nfr], b1f[nf2][nfr + 2]);      /* q2*q1 */
        }
        __syncthreads();
    }

    /* epilogue */
    float s = __uint_as_float(g_mxs[aslot]) * __uint_as_float(g_mxs[bslot]) *
              (1.f / 16129.f);
    int g = lane >> 2, tc = lane & 3;
    float hm = 0.f;
#pragma unroll
    for (int mf = 0; mf < 2; mf++) {
#pragma unroll
        for (int nf = 0; nf < 4; nf++) {
            int col = ncol0 + (nf >> 1) * 16 + (nf & 1) * 8 + tc * 2;
            float bx = bias[col], by = bias[col + 1];
            int* M_ = aM[mf][nf];
            int* S_ = aS[mf][nf];
            float v0 = s * ((float)M_[0] + (float)S_[0] * (1.f / 256.f)) + bx;
            float v1 = s * ((float)M_[1] + (float)S_[1] * (1.f / 256.f)) + by;
            float v2 = s * ((float)M_[2] + (float)S_[2] * (1.f / 256.f)) + bx;
            float v3 = s * ((float)M_[3] + (float)S_[3] * (1.f / 256.f)) + by;
            int rowA = row0 + mrow0 + mf * 16 + g;
            int rowB = rowA + 8;
            if (rowA < M) {
                *(float2*)(Cf + (size_t)rowA * HD + col) = make_float2(v0, v1);
                if (WMAX) hm = fmaxf(hm, fmaxf(fabsf(v0), fabsf(v1)));
            }
            if (rowB < M) {
                *(float2*)(Cf + (size_t)rowB * HD + col) = make_float2(v2, v3);
                if (WMAX) hm = fmaxf(hm, fmaxf(fabsf(v2), fabsf(v3)));
            }
        }
    }
    if (WMAX) warp_amax(hm, 2);
}

/* ---------------- host -------------------------------------------------------- */
extern "C" void kernel_launch(void* const* d_in, const int* in_sizes, int n_in,
                              void* d_out, int out_size) {
    const float* x       = (const float*)d_in[0];
    const int*   ei      = (const int*)  d_in[1];
    const int*   et      = (const int*)  d_in[3];
    const float* basis   = (const float*)d_in[4];
    const float* comp    = (const float*)d_in[5];
    const float* root    = (const float*)d_in[6];
    const float* bias1   = (const float*)d_in[7];
    const float* w_rel   = (const float*)d_in[8];
    const float* w_root2 = (const float*)d_in[9];
    const float* bias2   = (const float*)d_in[10];
    float* out = (float*)d_out;

    int N = in_sizes[0] / HD;
    int E = in_sizes[2];
    int B = in_sizes[4] / (HD * HD);
    int R = in_sizes[5] / B;
    int mpad = ((N + 127) / 128) * 128;
    int NR = N * R;
    size_t chU = (size_t)mpad * 32;

    float* p_h;
    uint32_t *p_aq1, *p_aq2, *p_a2q1, *p_a2q2;
    cudaGetSymbolAddress((void**)&p_h,    g_h);
    cudaGetSymbolAddress((void**)&p_aq1,  g_aq1);
    cudaGetSymbolAddress((void**)&p_aq2,  g_aq2);
    cudaGetSymbolAddress((void**)&p_a2q1, g_a2q1);
    cudaGetSymbolAddress((void**)&p_a2q2, g_a2q2);

    cudaFuncSetAttribute(k_mma<0>, cudaFuncAttributeMaxDynamicSharedMemorySize, S8_PIPE);
    cudaFuncSetAttribute(k_mma<1>, cudaFuncAttributeMaxDynamicSharedMemorySize, S8_PIPE);

    int nblk = (NR + 1023) / 1024;

    /* maxima init + x max */
    k_maxinit<<<1, 32>>>();
    k_maxabs<<<2048, 256>>>(x, (size_t)N * HD, 0);

    /* CSR build (deg2/cur2/done self-cleaning across calls) */
    k_hist<<<(E + 255) / 256, 256>>>(ei, et, E, R);
    k_scan<<<nblk, 1024>>>(NR, nblk);
    k_scatter<<<(E + 255) / 256, 256>>>(ei, et, E, R);

    /* per-(dst,rel) mean sums -> quantized A images   [profiled slot] */
    k_aggx<<<mpad * 32 / 256, 256>>>(x, N, mpad, chU);

    /* weights + B images (with maxima) */
    k_compute_w<<<R * HD, HD>>>(comp, basis, R, B);
    k_maxabs3<<<48, 256>>>(root, w_rel, w_root2);
    k_prep_b<<<11, 256>>>(root, w_rel, w_root2);

    /* layer 1: h = [S | X] @ [w;root] + bias1 (f32 out, h-max) */
    k_mma<1><<<mpad / 64, 256, S8_PIPE>>>(p_aq1, p_aq2, chU, R + 1, 0, 0, 1,
                                          bias1, p_h, N);
    /* nbr = sum h (f32 + max) ; then quantize nbr & h */
    k_agg2<<<mpad * 32 / 256, 256>>>(N, mpad);
    k_quant2<<<mpad * 32 / 256, 256>>>(N, mpad, chU);
    /* layer 2: out = [nbr | h] @ [w_rel; w_root2] + bias2 */
    k_mma<0><<<mpad / 64, 256, S8_PIPE>>>(p_a2q1, p_a2q2, chU, 2, 9, 2, 3,
                                          bias2, out, N);
}

// round 12
// speedup vs baseline: 1.8321x; 1.8321x over previous
#include <cuda_runtime.h>
#include <cuda_bf16.h>
#include <cstdint>

#define HD 128
#define MAXN 40000
#define MAXR 8
#define MAXE 640000
#define MAXNR (MAXN * MAXR)
#define MPADC (((MAXN + 127) / 128) * 128)

/* ---------------- scratch (static device globals; no allocation) ------------- */
__device__ float g_w[MAXR * HD * HD];
__device__ float g_h[(size_t)MPADC * HD];
__device__ int   g_deg2[MAXNR];
__device__ int   g_rsx[MAXNR + 1];
__device__ int   g_cur2[MAXNR];
__device__ int   g_csrc[MAXE];
__device__ int   g_bsum[512], g_boff[512];
__device__ unsigned short g_shi[(size_t)9 * MPADC * HD];
__device__ unsigned short g_slo[(size_t)9 * MPADC * HD];
__device__ unsigned short g_a2hi[(size_t)2 * MPADC * HD];
__device__ unsigned short g_a2lo[(size_t)2 * MPADC * HD];
#define BPITCH 136
#define BTILE  (128 * BPITCH)
__device__ unsigned short g_bimg[11 * 2 * BTILE];

/* ---------------- helpers ---------------------------------------------------- */
__device__ __forceinline__ uint32_t smem_u32(const void* p) {
    uint32_t a;
    asm("{ .reg .u64 t; cvta.to.shared.u64 t, %1; cvt.u32.u64 %0, t; }" : "=r"(a) : "l"(p));
    return a;
}
__device__ __forceinline__ void bsplit(float v, unsigned short& h, unsigned short& l) {
    __nv_bfloat16 bh = __float2bfloat16(v);
    h = __bfloat16_as_ushort(bh);
    l = __bfloat16_as_ushort(__float2bfloat16(v - __bfloat162float(bh)));
}
__device__ __forceinline__ uint32_t pack2(unsigned short a, unsigned short b) {
    return (uint32_t)a | ((uint32_t)b << 16);
}
__device__ __forceinline__ void split_store(float4 v, unsigned short* hi,
                                            unsigned short* lo, size_t idx) {
    unsigned short h0, l0, h1, l1, h2, l2, h3, l3;
    bsplit(v.x, h0, l0); bsplit(v.y, h1, l1);
    bsplit(v.z, h2, l2); bsplit(v.w, h3, l3);
    *(uint2*)&hi[idx] = make_uint2(pack2(h0, h1), pack2(h2, h3));
    *(uint2*)&lo[idx] = make_uint2(pack2(l0, l1), pack2(l2, l3));
}

#define LDSM4(r, addr)                                                             \
    asm volatile("ldmatrix.sync.aligned.m8n8.x4.shared.b16 {%0,%1,%2,%3}, [%4];"   \
        : "=r"((r)[0]), "=r"((r)[1]), "=r"((r)[2]), "=r"((r)[3]) : "r"(addr))

#define MMA16816(c, a, b0, b1)                                                     \
    asm volatile("mma.sync.aligned.m16n8k16.row.col.f32.bf16.bf16.f32 "            \
        "{%0,%1,%2,%3}, {%4,%5,%6,%7}, {%8,%9}, {%0,%1,%2,%3};"                    \
        : "+f"((c)[0]), "+f"((c)[1]), "+f"((c)[2]), "+f"((c)[3])                   \
        : "r"((a)[0]), "r"((a)[1]), "r"((a)[2]), "r"((a)[3]), "r"(b0), "r"(b1))

#define CPASYNC16(saddr, gptr)                                                     \
    asm volatile("cp.async.cg.shared.global [%0], [%1], 16;"                       \
        :: "r"(saddr), "l"(gptr))
#define CPCOMMIT() asm volatile("cp.async.commit_group;" ::: "memory")

/* ---------------- prep kernels ------------------------------------------------ */
__global__ void k_compute_w(const float* __restrict__ comp,
                            const float* __restrict__ basis, int R, int B) {
    int rd = blockIdx.x, h = threadIdx.x;
    int r = rd / HD, d = rd % HD;
    float s = 0.f;
    for (int b = 0; b < B; b++)
        s += comp[r * B + b] * basis[((size_t)b * HD + d) * HD + h];
    g_w[(size_t)rd * HD + h] = s;
}

__global__ void k_prep_b(const float* __restrict__ root, const float* __restrict__ wrel,
                         const float* __restrict__ wroot2) {
    int slot = blockIdx.x;
    const float* W = (slot < 8) ? (g_w + (size_t)slot * HD * HD)
                   : (slot == 8) ? root : (slot == 9) ? wrel : wroot2;
    unsigned short* hi = g_bimg + (size_t)(slot * 2 + 0) * BTILE;
    unsigned short* lo = g_bimg + (size_t)(slot * 2 + 1) * BTILE;
    for (int i = threadIdx.x; i < 128 * BPITCH; i += blockDim.x) {
        int n = i / BPITCH, k = i % BPITCH;
        float v = (k < HD) ? W[(size_t)k * HD + n] : 0.f;
        unsigned short h, l;
        bsplit(v, h, l);
        hi[i] = h;
        lo[i] = l;
    }
}

/* ---------------- per-(dst,rel) CSR ------------------------------------------ */
__global__ void k_hist(const int* __restrict__ ei, const int* __restrict__ et,
                       int E, int R) {
    int e = blockIdx.x * blockDim.x + threadIdx.x;
    if (e < E) atomicAdd(&g_deg2[ei[E + e] * R + et[e]], 1);
}

/* block-local warp-shuffle scan; no ticket, no fence */
__global__ void __launch_bounds__(1024) k_scan_a(int n) {
    __shared__ int swarp[32];
    int b = blockIdx.x, t = threadIdx.x, i = b * 1024 + t;
    int lane = t & 31, w = t >> 5;
    int v = 0;
    if (i < n) { v = g_deg2[i]; g_deg2[i] = 0; g_cur2[i] = 0; }
    int x = v;
#pragma unroll
    for (int off = 1; off < 32; off <<= 1) {
        int y = __shfl_up_sync(0xffffffffu, x, off);
        if (lane >= off) x += y;
    }
    if (lane == 31) swarp[w] = x;
    __syncthreads();
    if (w == 0) {
        int s = swarp[lane];
#pragma unroll
        for (int off = 1; off < 32; off <<= 1) {
            int y = __shfl_up_sync(0xffffffffu, s, off);
            if (lane >= off) s += y;
        }
        swarp[lane] = s;
    }
    __syncthreads();
    int inc = x + ((w > 0) ? swarp[w - 1] : 0);
    int ex = inc - v;
    if (i < n) g_rsx[i] = ex;
    if (i == n - 1) g_rsx[n] = ex + v;
    if (t == 1023) g_bsum[b] = inc;
}

/* single block: exclusive scan of per-block sums (nblk <= 512) */
__global__ void __launch_bounds__(512) k_scan_b(int nblk) {
    __shared__ int swarp[16];
    int t = threadIdx.x, lane = t & 31, w = t >> 5;
    int v = (t < nblk) ? g_bsum[t] : 0;
    int x = v;
#pragma unroll
    for (int off = 1; off < 32; off <<= 1) {
        int y = __shfl_up_sync(0xffffffffu, x, off);
        if (lane >= off) x += y;
    }
    if (lane == 31) swarp[w] = x;
    __syncthreads();
    if (w == 0 && lane < 16) {
        int s = swarp[lane];
#pragma unroll
        for (int off = 1; off < 16; off <<= 1) {
            int y = __shfl_up_sync(0x0000ffffu, s, off);
            if (lane >= off) s += y;
        }
        swarp[lane] = s;
    }
    __syncthreads();
    if (t < nblk) g_boff[t] = x + ((w > 0) ? swarp[w - 1] : 0) - v;
}

__global__ void k_scatter(const int* __restrict__ ei, const int* __restrict__ et,
                          int E, int R) {
    int e = blockIdx.x * blockDim.x + threadIdx.x;
    if (e >= E) return;
    int seg = ei[E + e] * R + et[e];
    int pos = g_rsx[seg] + g_boff[seg >> 10] + atomicAdd(&g_cur2[seg], 1);
    g_csrc[pos] = ei[e];
}

/* ---------------- S builder -------------------------------------------------- */
__global__ void __launch_bounds__(256) k_aggx(const float* __restrict__ x,
                                              int N, int mpad, size_t chStride) {
    int gt = blockIdx.x * blockDim.x + threadIdx.x;
    int node = gt >> 5, lane = gt & 31;
    if (node >= mpad) return;
    bool real = node < N;
    uint32_t bd = 0;
    if (real && lane < 9) {
        int seg = node * 8 + lane;
        bd = (uint32_t)(g_rsx[seg] + g_boff[seg >> 10]);
    }
    uint32_t a0 = __shfl_sync(0xffffffffu, bd, 0);
    uint32_t a8 = __shfl_sync(0xffffffffu, bd, 8);
    float inv = 1.f / fmaxf((float)(int)(a8 - a0), 1.f);
    size_t rowOff = (size_t)node * HD + lane * 4;

#pragma unroll
    for (int r = 0; r < 8; r++) {
        uint32_t s0 = __shfl_sync(0xffffffffu, bd, r);
        uint32_t s1 = __shfl_sync(0xffffffffu, bd, r + 1);
        float4 acc = make_float4(0.f, 0.f, 0.f, 0.f);
        uint32_t i = s0;
        for (; i + 2 <= s1; i += 2) {
            int sa = g_csrc[i], sb = g_csrc[i + 1];
            float4 va = ((const float4*)x)[(size_t)sa * 32 + lane];
            float4 vb = ((const float4*)x)[(size_t)sb * 32 + lane];
            acc.x += va.x + vb.x; acc.y += va.y + vb.y;
            acc.z += va.z + vb.z; acc.w += va.w + vb.w;
        }
        if (i < s1) {
            float4 va = ((const float4*)x)[(size_t)g_csrc[i] * 32 + lane];
            acc.x += va.x; acc.y += va.y; acc.z += va.z; acc.w += va.w;
        }
        acc.x *= inv; acc.y *= inv; acc.z *= inv; acc.w *= inv;
        split_store(acc, g_shi, g_slo, (size_t)r * chStride + rowOff);
    }
    float4 xv = make_float4(0.f, 0.f, 0.f, 0.f);
    if (real) xv = ((const float4*)x)[(size_t)node * 32 + lane];
    split_store(xv, g_shi, g_slo, (size_t)8 * chStride + rowOff);
}

/* ---------------- layer-2 neighbor sum --------------------------------------- */
__global__ void __launch_bounds__(256) k_agg2(int N, int mpad) {
    int gt = blockIdx.x * blockDim.x + threadIdx.x;
    int node = gt >> 5, lane = gt & 31;
    if (node >= mpad) return;
    uint32_t a0 = 0, a8 = 0;
    if (node < N) {
        int s = node * 8, s2 = s + 8;
        a0 = (uint32_t)(g_rsx[s] + g_boff[s >> 10]);
        a8 = (uint32_t)(g_rsx[s2] + g_boff[s2 >> 10]);
    }
    float4 acc = make_float4(0.f, 0.f, 0.f, 0.f);
    uint32_t i = a0;
    for (; i + 4 <= a8; i += 4) {
        int s0 = g_csrc[i], s1 = g_csrc[i + 1], s2 = g_csrc[i + 2], s3 = g_csrc[i + 3];
        float4 v0 = ((const float4*)g_h)[(size_t)s0 * 32 + lane];
        float4 v1 = ((const float4*)g_h)[(size_t)s1 * 32 + lane];
        float4 v2 = ((const float4*)g_h)[(size_t)s2 * 32 + lane];
        float4 v3 = ((const float4*)g_h)[(size_t)s3 * 32 + lane];
        acc.x += (v0.x + v1.x) + (v2.x + v3.x);
        acc.y += (v0.y + v1.y) + (v2.y + v3.y);
        acc.z += (v0.z + v1.z) + (v2.z + v3.z);
        acc.w += (v0.w + v1.w) + (v2.w + v3.w);
    }
    for (; i < a8; i++) {
        float4 v = ((const float4*)g_h)[(size_t)g_csrc[i] * 32 + lane];
        acc.x += v.x; acc.y += v.y; acc.z += v.z; acc.w += v.w;
    }
    split_store(acc, g_a2hi, g_a2lo, (size_t)node * HD + lane * 4);
}

/* ---------------- cp.async double-buffered split-bf16 mma.sync GEMM ----------- */
/* 2 stages x 104448 B; 1 CTA/SM; M-tile 64, N=128, K=128 per chunk  (round 9)  */
#define SM_AH 0
#define SM_AL 17408
#define SM_BH 34816
#define SM_BL 69632
#define STG_SZ 104448
#define SM_PIPE (2 * STG_SZ)
#define APITCHB 272

__device__ __forceinline__ void prefetch_chunk(
    uint32_t sb, const unsigned short* __restrict__ ah,
    const unsigned short* __restrict__ al,
    const unsigned short* __restrict__ bh,
    const unsigned short* __restrict__ bl, int tid)
{
#pragma unroll
    for (int i = 0; i < 4; i++) {
        int idx = tid + i * 256;
        int r = idx >> 4, c = idx & 15;
        CPASYNC16(sb + SM_AH + r * APITCHB + c * 16, ah + (size_t)r * HD + c * 8);
        CPASYNC16(sb + SM_AL + r * APITCHB + c * 16, al + (size_t)r * HD + c * 8);
    }
#pragma unroll
    for (int i = 0; i < 9; i++) {
        int idx = tid + i * 256;
        if (idx < 2176) {
            CPASYNC16(sb + SM_BH + idx * 16, bh + (size_t)idx * 8);
            CPASYNC16(sb + SM_BL + idx * 16, bl + (size_t)idx * 8);
        }
    }
}

template<int WIMG>
__global__ void __launch_bounds__(256) k_mma(
    const unsigned short* __restrict__ aHi, const unsigned short* __restrict__ aLo,
    size_t aStride, int nch, int bslot0, const float* __restrict__ bias,
    float* __restrict__ Cf, unsigned short* __restrict__ imgHi,
    unsigned short* __restrict__ imgLo, int M)
{
    extern __shared__ unsigned char sm[];
    uint32_t sb0 = smem_u32(sm);
    int tid = threadIdx.x, lane = tid & 31, wid = tid >> 5;
    int row0 = blockIdx.x * 64;
    int wr = wid & 1, wc = wid >> 1;
    int mrow0 = wr * 32, ncol0 = wc * 32;

    float acc[2][4][4];
#pragma unroll
    for (int a = 0; a < 2; a++)
#pragma unroll
        for (int b = 0; b < 4; b++)
#pragma unroll
            for (int c = 0; c < 4; c++) acc[a][b][c] = 0.f;

    /* prefetch chunk 0 -> stage 0 */
    {
        const unsigned short* ah = aHi + (size_t)row0 * HD;
        const unsigned short* al = aLo + (size_t)row0 * HD;
        const unsigned short* bh = g_bimg + (size_t)(bslot0 * 2 + 0) * BTILE;
        prefetch_chunk(sb0, ah, al, bh, bh + BTILE, tid);
        CPCOMMIT();
    }

    for (int ch = 0; ch < nch; ch++) {
        if (ch + 1 < nch) {
            const unsigned short* ah = aHi + (size_t)(ch + 1) * aStride + (size_t)row0 * HD;
            const unsigned short* al = aLo + (size_t)(ch + 1) * aStride + (size_t)row0 * HD;
            const unsigned short* bh = g_bimg + (size_t)((bslot0 + ch + 1) * 2) * BTILE;
            prefetch_chunk(sb0 + ((ch + 1) & 1) * STG_SZ, ah, al, bh, bh + BTILE, tid);
            CPCOMMIT();
            asm volatile("cp.async.wait_group 1;" ::: "memory");
        } else {
            asm volatile("cp.async.wait_group 0;" ::: "memory");
        }
        __syncthreads();

        uint32_t sbase = sb0 + (ch & 1) * STG_SZ;
#pragma unroll
        for (int ks = 0; ks < 8; ks++) {
            uint32_t koff = ks * 32 + (lane >> 4) * 16;
            uint32_t ra[2][4], rl[2][4];
#pragma unroll
            for (int mf = 0; mf < 2; mf++) {
                uint32_t arow = (uint32_t)(mrow0 + mf * 16 + (lane & 15)) * APITCHB + koff;
                LDSM4(ra[mf], sbase + SM_AH + arow);
                LDSM4(rl[mf], sbase + SM_AL + arow);
            }
#pragma unroll
            for (int nf2 = 0; nf2 < 2; nf2++) {
                uint32_t brow = (uint32_t)(ncol0 + nf2 * 16 + (lane & 15)) * APITCHB + koff;
                uint32_t bh[4], bl[4];
                LDSM4(bh, sbase + SM_BH + brow);
                LDSM4(bl, sbase + SM_BL + brow);
#pragma unroll
                for (int mf = 0; mf < 2; mf++) {
#pragma unroll
                    for (int nfr = 0; nfr < 2; nfr++) {
                        float* c = acc[mf][nf2 * 2 + nfr];
                        MMA16816(c, ra[mf], bh[nfr], bh[nfr + 2]);   /* hi*hi */
                        MMA16816(c, rl[mf], bh[nfr], bh[nfr + 2]);   /* lo*hi */
                        MMA16816(c, ra[mf], bl[nfr], bl[nfr + 2]);   /* hi*lo */
                    }
                }
            }
        }
        __syncthreads();
    }

    /* epilogue */
    int g = lane >> 2, tc = lane & 3;
#pragma unroll
    for (int mf = 0; mf < 2; mf++) {
#pragma unroll
        for (int nf = 0; nf < 4; nf++) {
            int col = ncol0 + (nf >> 1) * 16 + (nf & 1) * 8 + tc * 2;
            float bx = bias[col], by = bias[col + 1];
            float* c = acc[mf][nf];
            int rowA = row0 + mrow0 + mf * 16 + g;
            int rowB = rowA + 8;
            float v0 = c[0] + bx, v1 = c[1] + by;
            float v2 = c[2] + bx, v3 = c[3] + by;
            if (rowA < M) *(float2*)(Cf + (size_t)rowA * HD + col) = make_float2(v0, v1);
            if (rowB < M) *(float2*)(Cf + (size_t)rowB * HD + col) = make_float2(v2, v3);
            if (WIMG) {
                unsigned short h0, l0, h1, l1;
                bsplit(v0, h0, l0); bsplit(v1, h1, l1);
                *(uint32_t*)&imgHi[(size_t)rowA * HD + col] = pack2(h0, h1);
                *(uint32_t*)&imgLo[(size_t)rowA * HD + col] = pack2(l0, l1);
                bsplit(v2, h0, l0); bsplit(v3, h1, l1);
                *(uint32_t*)&imgHi[(size_t)rowB * HD + col] = pack2(h0, h1);
                *(uint32_t*)&imgLo[(size_t)rowB * HD + col] = pack2(l0, l1);
            }
        }
    }
}

/* ---------------- host -------------------------------------------------------- */
extern "C" void kernel_launch(void* const* d_in, const int* in_sizes, int n_in,
                              void* d_out, int out_size) {
    const float* x       = (const float*)d_in[0];
    const int*   ei      = (const int*)  d_in[1];
    const int*   et      = (const int*)  d_in[3];
    const float* basis   = (const float*)d_in[4];
    const float* comp    = (const float*)d_in[5];
    const float* root    = (const float*)d_in[6];
    const float* bias1   = (const float*)d_in[7];
    const float* w_rel   = (const float*)d_in[8];
    const float* w_root2 = (const float*)d_in[9];
    const float* bias2   = (const float*)d_in[10];
    float* out = (float*)d_out;

    int N = in_sizes[0] / HD;
    int E = in_sizes[2];
    int B = in_sizes[4] / (HD * HD);
    int R = in_sizes[5] / B;
    int mpad = ((N + 127) / 128) * 128;
    int NR = N * R;
    size_t chStride = (size_t)mpad * HD;

    float* p_h;
    unsigned short *p_shi, *p_slo, *p_a2hi, *p_a2lo;
    cudaGetSymbolAddress((void**)&p_h,    g_h);
    cudaGetSymbolAddress((void**)&p_shi,  g_shi);
    cudaGetSymbolAddress((void**)&p_slo,  g_slo);
    cudaGetSymbolAddress((void**)&p_a2hi, g_a2hi);
    cudaGetSymbolAddress((void**)&p_a2lo, g_a2lo);

    cudaFuncSetAttribute(k_mma<0>, cudaFuncAttributeMaxDynamicSharedMemorySize, SM_PIPE);
    cudaFuncSetAttribute(k_mma<1>, cudaFuncAttributeMaxDynamicSharedMemorySize, SM_PIPE);

    int nblk = (NR + 1023) / 1024;

    /* CSR build (deg2/cur2 self-cleaning across calls) */
    k_hist<<<(E + 255) / 256, 256>>>(ei, et, E, R);
    k_scan_a<<<nblk, 1024>>>(NR);
    k_scan_b<<<1, 512>>>(nblk);
    k_scatter<<<(E + 255) / 256, 256>>>(ei, et, E, R);

    /* per-(dst,rel) mean sums -> S images + X chunk */
    k_aggx<<<mpad * 32 / 256, 256>>>(x, N, mpad, chStride);

    /* weights + B operand images */
    k_compute_w<<<R * HD, HD>>>(comp, basis, R, B);
    k_prep_b<<<11, 256>>>(root, w_rel, w_root2);

    /* layer 1: h = [S | X] @ [w;root] + bias1, emit h image (chunk 1) */
    k_mma<1><<<mpad / 64, 256, SM_PIPE>>>(p_shi, p_slo, chStride, R + 1, 0, bias1,
                                          p_h, p_a2hi + chStride, p_a2lo + chStride, N);
    /* nbr -> image (chunk 0) */
    k_agg2<<<mpad * 32 / 256, 256>>>(N, mpad);
    /* layer 2: out = [nbr | h] @ [w_rel; w_root2] + bias2 */
    k_mma<0><<<mpad / 64, 256, SM_PIPE>>>(p_a2hi, p_a2lo, chStride, 2, 9, bias2,
                                          out, nullptr, nullptr, N);
}